// round 14
// baseline (speedup 1.0000x reference)
#include <cuda_runtime.h>
#include <math.h>

#define KSZ   1024
#define WNUM  1023
#define BNUM  2
#define NDL   16
#define TPB   256
#define TOTAL_FLOATS 33521664u   // 16 * 2 * 1023 * 1024 real-part floats
#define IDX2_STRIDE 520

__device__ float2 g_idx2[NDL * IDX2_STRIDE];  // (idx[j], idx[(1024-j)&1023]), j<=512
__device__ float4 g_chp4[IDX2_STRIDE];        // (chp[jj].x, chp[jj].y, chp[j].x, chp[j].y)
__device__ float2 g_tw[KSZ];                  // e^{-2pi i r/1024}
__device__ float2 g_hpair[KSZ];               // (hann[k], hann[k+1])

__device__ __forceinline__ float2 c_mul(float2 a, float2 b) {
    return make_float2(fmaf(a.x, b.x, -a.y * b.y), fmaf(a.x, b.y, a.y * b.x));
}
// conj(t) * d  (4 FMA, conj folded)
__device__ __forceinline__ float2 c_mulcj(float2 t, float2 d) {
    return make_float2(fmaf(t.x, d.x, t.y * d.y), fmaf(t.x, d.y, -t.y * d.x));
}
__device__ __forceinline__ int clampi(int v, int lo, int hi) {
    return v < lo ? lo : (v > hi ? hi : v);
}

// ---- packed f32x2 primitives (emit Blackwell FFMA2 / FADD2) ----
__device__ __forceinline__ float2 f2add(float2 a, float2 b) {
    float2 d;
    asm("{\n\t.reg .b64 ra, rb, rd;\n\t"
        "mov.b64 ra, {%2, %3};\n\tmov.b64 rb, {%4, %5};\n\t"
        "add.rn.f32x2 rd, ra, rb;\n\t"
        "mov.b64 {%0, %1}, rd;\n\t}"
        : "=f"(d.x), "=f"(d.y)
        : "f"(a.x), "f"(a.y), "f"(b.x), "f"(b.y));
    return d;
}
__device__ __forceinline__ float2 f2fma(float2 a, float2 b, float2 c) {  // a*b + c
    float2 d;
    asm("{\n\t.reg .b64 ra, rb, rc, rd;\n\t"
        "mov.b64 ra, {%2, %3};\n\tmov.b64 rb, {%4, %5};\n\tmov.b64 rc, {%6, %7};\n\t"
        "fma.rn.f32x2 rd, ra, rb, rc;\n\t"
        "mov.b64 {%0, %1}, rd;\n\t}"
        : "=f"(d.x), "=f"(d.y)
        : "f"(a.x), "f"(a.y), "f"(b.x), "f"(b.y), "f"(c.x), "f"(c.y));
    return d;
}
#define C_M1M1 make_float2(-1.f, -1.f)
#define C_M1P1 make_float2(-1.f,  1.f)
#define C_P1M1 make_float2( 1.f, -1.f)
__device__ __forceinline__ float2 f2sub(float2 a, float2 b) { return f2fma(b, C_M1M1, a); }

// dft16 slot<->frequency involution
__device__ __forceinline__ constexpr int F16(int s) { return (s >> 2) + 4 * (s & 3); }

// positive-sign radix-4 butterfly (w4 = +i), packed
__device__ __forceinline__ void r4p(float2& x0, float2& x1, float2& x2, float2& x3) {
    const float2 t0 = f2add(x0, x2), t1 = f2sub(x0, x2);
    const float2 t2 = f2add(x1, x3), bd = f2sub(x1, x3);
    const float2 bds = make_float2(bd.y, bd.x);
    x0 = f2add(t0, t2);
    x2 = f2sub(t0, t2);
    x1 = f2fma(bds, C_M1P1, t1);
    x3 = f2fma(bds, C_P1M1, t1);
}

// 16-point POSITIVE DFT in registers; Y[F16(s)] lands in slot s.
__device__ __forceinline__ void dft16p(float2 X[16]) {
    r4p(X[0], X[4], X[8],  X[12]);
    r4p(X[1], X[5], X[9],  X[13]);
    r4p(X[2], X[6], X[10], X[14]);
    r4p(X[3], X[7], X[11], X[15]);
    const float C1 = 0.9238795325112867f, S1 = 0.3826834323650898f, R2 = 0.7071067811865476f;
    X[5]  = c_mul(X[5],  make_float2( C1,  S1));
    X[9]  = c_mul(X[9],  make_float2( R2,  R2));
    X[13] = c_mul(X[13], make_float2( S1,  C1));
    X[6]  = c_mul(X[6],  make_float2( R2,  R2));
    X[10] = make_float2(-X[10].y, X[10].x);
    X[14] = c_mul(X[14], make_float2(-R2,  R2));
    X[7]  = c_mul(X[7],  make_float2( S1,  C1));
    X[11] = c_mul(X[11], make_float2(-R2,  R2));
    X[15] = c_mul(X[15], make_float2(-C1, -S1));
    r4p(X[0],  X[1],  X[2],  X[3]);
    r4p(X[4],  X[5],  X[6],  X[7]);
    r4p(X[8],  X[9],  X[10], X[11]);
    r4p(X[12], X[13], X[14], X[15]);
}

// e^{+2pi i s/32}
__device__ __constant__ float2 CW32P[16] = {
    { 1.0000000000f, 0.0000000000f}, { 0.9807852804f, 0.1950903220f},
    { 0.9238795325f, 0.3826834324f}, { 0.8314696123f, 0.5555702330f},
    { 0.7071067812f, 0.7071067812f}, { 0.5555702330f, 0.8314696123f},
    { 0.3826834324f, 0.9238795325f}, { 0.1950903220f, 0.9807852804f},
    { 0.0000000000f, 1.0000000000f}, {-0.1950903220f, 0.9807852804f},
    {-0.3826834324f, 0.9238795325f}, {-0.5555702330f, 0.8314696123f},
    {-0.7071067812f, 0.7071067812f}, {-0.8314696123f, 0.5555702330f},
    {-0.9238795325f, 0.3826834324f}, {-0.9807852804f, 0.1950903220f}};

// ---------------------------------------------------------------------------
__global__ void prep_kernel(const float* __restrict__ dlnf, unsigned int dlnf_n) {
    const int k = threadIdx.x;
    const int bid = blockIdx.x;
    if (bid < NDL) {
        __shared__ float sidx[KSZ];
        __shared__ float sh_em1, sh_beta;
        if (k == 0) {
            const float beta = (bid < (int)dlnf_n) ? 2.0f * dlnf[bid] : 0.0f;
            sh_beta = beta;
            sh_em1 = (float)exp((double)beta) - 1.0f;   // fast-math-proof
        }
        __syncthreads();
        const float beta = sh_beta, em1 = sh_em1;
        float tsrc;
        if (fabsf(beta) < 1e-8f) {
            tsrc = -1.0f + (float)k * (2.0f / 1023.0f);
        } else {
            const float tau = (float)k * (1.0f / 1023.0f);
            tsrc = (2.0f / beta) * log1pf(tau * em1) - 1.0f;
        }
        sidx[k] = (tsrc + 1.0f) * 0.5f * 1023.0f;
        __syncthreads();
        if (k <= 512)
            g_idx2[bid * IDX2_STRIDE + k] = make_float2(sidx[k], sidx[(1024 - k) & 1023]);
    } else {
        __shared__ float2 schp[KSZ];
        const float kf = (float)k;
        float s, c;
        __sincosf(-6.283185307179586f * kf * (1.0f / 1024.0f), &s, &c);
        g_tw[k] = make_float2(c, s);
        const float t = fmaf(2.0f * (1.0f / 1023.0f), kf, -1.0f);
        __sincosf(-0.5f * t * t, &s, &c);
        schp[k] = make_float2(0.5f * c, 0.5f * s);
        const float h0 = 0.5f * (1.0f - __cosf(6.283185307179586f * kf * (1.0f / 1024.0f)));
        const float h1 = (k < KSZ - 1)
            ? 0.5f * (1.0f - __cosf(6.283185307179586f * (kf + 1.0f) * (1.0f / 1024.0f)))
            : 0.0f;
        g_hpair[k] = make_float2(h0, h1);
        __syncthreads();
        if (k <= 512) {
            const float2 cj  = schp[k];
            const float2 cjj = schp[(1024 - k) & 1023];
            g_chp4[k] = make_float4(cjj.x, cjj.y, cj.x, cj.y);
        }
    }
}

// hermitian base from two resampled values + paired chirp
__device__ __forceinline__ float2 hbase(float r1, float r2, float4 cp) {
    return make_float2(fmaf(r1, cp.z, r2 * cp.x), fmaf(r2, cp.y, -r1 * cp.w));
}
// pack2 combine: U = A + i*conj(t)*D with A = wq + conj(pm), D = wq - conj(pm)
__device__ __forceinline__ float2 pack2(float2 wq, float2 pm, float2 t) {
    const float2 A = f2fma(pm, C_P1M1, wq);
    const float2 D = f2fma(pm, C_M1P1, wq);
    const float2 B = c_mulcj(t, D);
    return f2fma(make_float2(B.y, B.x), C_M1P1, A);
}

// ---------------------------------------------------------------------------
// One CTA per TWO (b,w) windows; 8 warps; warp = d in {wid, wid+8}.
// Both windows flow through pack/FFT/store INTERLEAVED via dual xch buffers:
// shared twiddle chains + doubled ILP + half the syncwarps.
// ---------------------------------------------------------------------------
#define ROWS  17
#define XROWS 33          // row 32 = shifted lane-0 mirror row (uniform pack2)
#define XCHSZ (XROWS * ROWS)   // 561 float2 per buffer
__global__ void __launch_bounds__(TPB, 2) stft_kernel(const float* __restrict__ x,
                                                      float* __restrict__ out,
                                                      unsigned int x_n,
                                                      unsigned int cap) {
    extern __shared__ float sm[];
    float4* wp4 = (float4*)sm;                                // 1024 f4 = 16 KB
    const int tid  = threadIdx.x;
    const int lane = tid & 31;
    const int wid  = tid >> 5;
    float2* xchA = (float2*)(sm + 4 * KSZ) + (size_t)(2 * wid) * XCHSZ;
    float2* xchB = xchA + XCHSZ;

    const int bw0 = 2 * blockIdx.x;
    const int bw1 = bw0 + 1;
    const int b0 = bw0 / WNUM, w0 = bw0 - b0 * WNUM;
    const int b1 = bw1 / WNUM, w1 = bw1 - b1 * WNUM;
    const unsigned int xbase0 = (unsigned int)b0 * 524288u + (unsigned int)w0 * 512u;
    const unsigned int xbase1 = (unsigned int)b1 * 524288u + (unsigned int)w1 * 512u;

    // Build combined windowed table: wp4[k] = (w0[k], w0[k+1], w1[k], w1[k+1])
#pragma unroll
    for (int q = 0; q < 4; q++) {
        const int k = tid + TPB * q;
        const float2 hp = g_hpair[k];
        const unsigned int gi0 = xbase0 + (unsigned int)k;
        const float a0 = (gi0 < x_n) ? x[gi0] : 0.0f;
        const float a1 = (gi0 + 1u < x_n) ? x[gi0 + 1u] : 0.0f;
        const unsigned int gi1 = xbase1 + (unsigned int)k;
        const float c0 = (gi1 < x_n) ? x[gi1] : 0.0f;
        const float c1 = (gi1 + 1u < x_n) ? x[gi1 + 1u] : 0.0f;
        wp4[k] = make_float4(a0 * hp.x, a1 * hp.y, c0 * hp.x, c1 * hp.y);
    }
    const float2 g2 = g_tw[2 * lane];
    const float2 base = make_float2(g2.x, -g2.y);              // e^{+2pi i lane/512}
    const float2 b2 = c_mul(base, base);
    const float2 b3 = c_mul(b2, base);
    const float2 b4 = c_mul(b2, b2);
    const int pa2 = 32 - lane;                                 // 0 -> 32 (mirror row)
    const int r   = lane & 15;
    const int h   = lane >> 4;
    const float2 csgn = h ? C_M1M1 : make_float2(1.f, 1.f);
    __syncthreads();

#pragma unroll 1
    for (int it = 0; it < 2; it++) {
        const int d = wid + 8 * it;
        const float2* id2 = g_idx2 + d * IDX2_STRIDE;

        // ---- pack stage 1 (both windows; tables + lo/frac computed once) ----
        __syncwarp();    // previous iteration's xch reads complete
        float2 wb0[16], wb1[16];
#pragma unroll
        for (int bq = 0; bq < 16; bq++) {
            const int j = lane + 32 * bq;
            const float2 ix = id2[j];
            const float4 cp = g_chp4[j];
            const int lo1 = clampi((int)ix.x, 0, 1022);
            const float f1 = ix.x - (float)lo1;
            const float4 qa = wp4[lo1];
            const float va0 = fmaf(f1, qa.y - qa.x, qa.x);
            const float va1 = fmaf(f1, qa.w - qa.z, qa.z);
            const int lo2 = clampi((int)ix.y, 0, 1022);
            const float f2 = ix.y - (float)lo2;
            const float4 qb = wp4[lo2];
            const float vb0 = fmaf(f2, qb.y - qb.x, qb.x);
            const float vb1 = fmaf(f2, qb.w - qb.z, qb.z);
            wb0[bq] = hbase(va0, vb0, cp);
            wb1[bq] = hbase(va1, vb1, cp);
            xchA[lane * ROWS + bq] = wb0[bq];
            xchB[lane * ROWS + bq] = wb1[bq];
            if (lane == 0 && bq >= 1) {
                xchA[32 * ROWS + bq - 1] = wb0[bq];
                xchB[32 * ROWS + bq - 1] = wb1[bq];
            }
        }
        {
            const float2 ix = id2[512];
            const int lo = clampi((int)ix.x, 0, 1022);
            const float f = ix.x - (float)lo;
            const float4 qa = wp4[lo];
            const float cz2 = 2.0f * g_chp4[512].z;
            if (lane == 0) {
                xchA[32 * ROWS + 15] = make_float2(fmaf(f, qa.y - qa.x, qa.x) * cz2, 0.0f);
                xchB[32 * ROWS + 15] = make_float2(fmaf(f, qa.w - qa.z, qa.z) * cz2, 0.0f);
            }
        }
        __syncwarp();

        // ---- pack stage 2, both windows (shared g_tw load) ----
#pragma unroll
        for (int bq = 0; bq < 16; bq++) {
            const float2 pmA = xchA[pa2 * ROWS + 15 - bq];     // h[512-q] win0
            const float2 pmB = xchB[pa2 * ROWS + 15 - bq];     // h[512-q] win1
            const float2 t = __ldg(&g_tw[lane + 32 * bq]);     // e^{-2pi i q/1024}
            wb0[bq] = pack2(wb0[bq], pmA, t);
            wb1[bq] = pack2(wb1[bq], pmB, t);
        }

        // ---- 512-pt positive FFT step 1, both windows (2x ILP) ----
        dft16p(wb0);
        dft16p(wb1);

        // ---- step 2: shared twiddle chain, write both transposed ----
        __syncwarp();    // pack2 mirror reads done before overwrite
        {
            float2 t1 = base, t2 = b2, t3 = b3, t4 = b4;
            xchA[lane * ROWS + 0] = wb0[0];
            xchB[lane * ROWS + 0] = wb1[0];
#pragma unroll
            for (int rr = 1; rr < 16; rr++) {
                float2 wc;
                switch (rr & 3) {
                    case 1: wc = t1; if (rr < 12) t1 = c_mul(t1, b4); break;
                    case 2: wc = t2; if (rr < 12) t2 = c_mul(t2, b4); break;
                    case 3: wc = t3; if (rr < 12) t3 = c_mul(t3, b4); break;
                    default: wc = t4; if (rr < 12) t4 = c_mul(t4, b4); break;
                }
                const int s = F16(rr);
                xchA[lane * ROWS + rr] = c_mul(wb0[s], wc);
                xchB[lane * ROWS + rr] = c_mul(wb1[s], wc);
            }
        }
        __syncwarp();

        // ---- step 3: gather both, 16-pt DFT both (2x ILP) ----
        float2 G0[16], G1[16];
#pragma unroll
        for (int j = 0; j < 16; j++) {
            G0[j] = xchA[(2 * j + h) * ROWS + r];
            G1[j] = xchB[(2 * j + h) * ROWS + r];
        }
        dft16p(G0);
        dft16p(G1);

        // ---- step 4: radix-2 combine + store, both windows ----
        const unsigned int ob0 = ((unsigned int)d * (BNUM * WNUM) + (unsigned int)bw0) * KSZ;
        const unsigned int ob1 = ((unsigned int)d * (BNUM * WNUM) + (unsigned int)bw1) * KSZ;
        if (cap >= TOTAL_FLOATS) {
#pragma unroll
            for (int s = 0; s < 16; s++) {
                const int sp = F16(s);
                const unsigned int off = 2u * (unsigned int)(r + 16 * sp + 256 * h);
                const float2 cw = CW32P[sp];
                {
                    const float2 own = G0[s];
                    float2 oth;
                    oth.x = __shfl_xor_sync(0xffffffffu, own.x, 16);
                    oth.y = __shfl_xor_sync(0xffffffffu, own.y, 16);
                    const float2 E = h ? oth : own;
                    const float2 O = h ? own : oth;
                    *(float2*)(out + ob0 + off) = f2fma(c_mul(O, cw), csgn, E);
                }
                {
                    const float2 own = G1[s];
                    float2 oth;
                    oth.x = __shfl_xor_sync(0xffffffffu, own.x, 16);
                    oth.y = __shfl_xor_sync(0xffffffffu, own.y, 16);
                    const float2 E = h ? oth : own;
                    const float2 O = h ? own : oth;
                    *(float2*)(out + ob1 + off) = f2fma(c_mul(O, cw), csgn, E);
                }
            }
        } else {
#pragma unroll
            for (int s = 0; s < 16; s++) {
                const int sp = F16(s);
                const unsigned int off = 2u * (unsigned int)(r + 16 * sp + 256 * h);
                const float2 cw = CW32P[sp];
                {
                    const float2 own = G0[s];
                    float2 oth;
                    oth.x = __shfl_xor_sync(0xffffffffu, own.x, 16);
                    oth.y = __shfl_xor_sync(0xffffffffu, own.y, 16);
                    const float2 E = h ? oth : own;
                    const float2 O = h ? own : oth;
                    const float2 res = f2fma(c_mul(O, cw), csgn, E);
                    const unsigned int fo = ob0 + off;
                    if (fo + 1u < cap) *(float2*)(out + fo) = res;
                    else if (fo < cap) out[fo] = res.x;
                }
                {
                    const float2 own = G1[s];
                    float2 oth;
                    oth.x = __shfl_xor_sync(0xffffffffu, own.x, 16);
                    oth.y = __shfl_xor_sync(0xffffffffu, own.y, 16);
                    const float2 E = h ? oth : own;
                    const float2 O = h ? own : oth;
                    const float2 res = f2fma(c_mul(O, cw), csgn, E);
                    const unsigned int fo = ob1 + off;
                    if (fo + 1u < cap) *(float2*)(out + fo) = res;
                    else if (fo < cap) out[fo] = res.x;
                }
            }
        }
    }
}

#define SMEM_BYTES (KSZ * 16 + 8 * 2 * XCHSZ * 8)   // 16384 + 71808 = 88192

// ---------------------------------------------------------------------------
extern "C" void kernel_launch(void* const* d_in, const int* in_sizes, int n_in,
                              void* d_out, int out_size) {
    if (!d_in || !in_sizes || !d_out || n_in < 1) return;

    const float* x = nullptr;   long long xn = -1;
    const float* dl = nullptr;  long long dn = 0;
    for (int i = 0; i < n_in; i++) {
        if (!d_in[i]) continue;
        if ((long long)in_sizes[i] > xn) { xn = in_sizes[i]; x = (const float*)d_in[i]; }
    }
    for (int i = 0; i < n_in; i++) {
        if (!d_in[i] || (const float*)d_in[i] == x) continue;
        dl = (const float*)d_in[i]; dn = in_sizes[i];
    }
    if (!x || xn <= 0) return;
    if (!dl) { dl = x; dn = 0; }

    long long cap = (long long)out_size;
    if (cap > (long long)TOTAL_FLOATS) cap = TOTAL_FLOATS;
    if (cap < 0) cap = 0;

    cudaFuncSetAttribute(stft_kernel, cudaFuncAttributeMaxDynamicSharedMemorySize, SMEM_BYTES);

    prep_kernel<<<NDL + 1, KSZ>>>(dl, (unsigned int)dn);
    stft_kernel<<<(BNUM * WNUM) / 2, TPB, SMEM_BYTES>>>(x, (float*)d_out,
                                                        (unsigned int)xn, (unsigned int)cap);
}

// round 15
// speedup vs baseline: 1.4942x; 1.4942x over previous
#include <cuda_runtime.h>
#include <math.h>

#define KSZ   1024
#define WNUM  1023
#define BNUM  2
#define NDL   16
#define TPB   256
#define TOTAL_FLOATS 33521664u   // 16 * 2 * 1023 * 1024 real-part floats
#define IDX2_STRIDE 520

__device__ float2 g_idx2[NDL * IDX2_STRIDE];  // (idx[j], idx[(1024-j)&1023]), j<=512
__device__ float4 g_chp4[IDX2_STRIDE];        // (chp[jj].x, chp[jj].y, chp[j].x, chp[j].y)
__device__ float2 g_tw[KSZ];                  // e^{-2pi i r/1024}
__device__ float2 g_hpair[KSZ];               // (hann[k], hann[k+1])

__device__ __forceinline__ float2 c_mul(float2 a, float2 b) {
    return make_float2(fmaf(a.x, b.x, -a.y * b.y), fmaf(a.x, b.y, a.y * b.x));
}
// conj(t) * d  (4 FMA, conj folded)
__device__ __forceinline__ float2 c_mulcj(float2 t, float2 d) {
    return make_float2(fmaf(t.x, d.x, t.y * d.y), fmaf(t.x, d.y, -t.y * d.x));
}
__device__ __forceinline__ int clampi(int v, int lo, int hi) {
    return v < lo ? lo : (v > hi ? hi : v);
}

// ---- packed f32x2 primitives (emit Blackwell FFMA2 / FADD2) ----
__device__ __forceinline__ float2 f2add(float2 a, float2 b) {
    float2 d;
    asm("{\n\t.reg .b64 ra, rb, rd;\n\t"
        "mov.b64 ra, {%2, %3};\n\tmov.b64 rb, {%4, %5};\n\t"
        "add.rn.f32x2 rd, ra, rb;\n\t"
        "mov.b64 {%0, %1}, rd;\n\t}"
        : "=f"(d.x), "=f"(d.y)
        : "f"(a.x), "f"(a.y), "f"(b.x), "f"(b.y));
    return d;
}
__device__ __forceinline__ float2 f2fma(float2 a, float2 b, float2 c) {  // a*b + c
    float2 d;
    asm("{\n\t.reg .b64 ra, rb, rc, rd;\n\t"
        "mov.b64 ra, {%2, %3};\n\tmov.b64 rb, {%4, %5};\n\tmov.b64 rc, {%6, %7};\n\t"
        "fma.rn.f32x2 rd, ra, rb, rc;\n\t"
        "mov.b64 {%0, %1}, rd;\n\t}"
        : "=f"(d.x), "=f"(d.y)
        : "f"(a.x), "f"(a.y), "f"(b.x), "f"(b.y), "f"(c.x), "f"(c.y));
    return d;
}
#define C_M1M1 make_float2(-1.f, -1.f)
#define C_M1P1 make_float2(-1.f,  1.f)
#define C_P1M1 make_float2( 1.f, -1.f)
__device__ __forceinline__ float2 f2sub(float2 a, float2 b) { return f2fma(b, C_M1M1, a); }

// dft16 slot<->frequency involution
__device__ __forceinline__ constexpr int F16(int s) { return (s >> 2) + 4 * (s & 3); }

// positive-sign radix-4 butterfly (w4 = +i), packed
__device__ __forceinline__ void r4p(float2& x0, float2& x1, float2& x2, float2& x3) {
    const float2 t0 = f2add(x0, x2), t1 = f2sub(x0, x2);
    const float2 t2 = f2add(x1, x3), bd = f2sub(x1, x3);
    const float2 bds = make_float2(bd.y, bd.x);
    x0 = f2add(t0, t2);
    x2 = f2sub(t0, t2);
    x1 = f2fma(bds, C_M1P1, t1);
    x3 = f2fma(bds, C_P1M1, t1);
}

// 16-point POSITIVE DFT in registers; Y[F16(s)] lands in slot s.
__device__ __forceinline__ void dft16p(float2 X[16]) {
    r4p(X[0], X[4], X[8],  X[12]);
    r4p(X[1], X[5], X[9],  X[13]);
    r4p(X[2], X[6], X[10], X[14]);
    r4p(X[3], X[7], X[11], X[15]);
    const float C1 = 0.9238795325112867f, S1 = 0.3826834323650898f, R2 = 0.7071067811865476f;
    X[5]  = c_mul(X[5],  make_float2( C1,  S1));
    X[9]  = c_mul(X[9],  make_float2( R2,  R2));
    X[13] = c_mul(X[13], make_float2( S1,  C1));
    X[6]  = c_mul(X[6],  make_float2( R2,  R2));
    X[10] = make_float2(-X[10].y, X[10].x);
    X[14] = c_mul(X[14], make_float2(-R2,  R2));
    X[7]  = c_mul(X[7],  make_float2( S1,  C1));
    X[11] = c_mul(X[11], make_float2(-R2,  R2));
    X[15] = c_mul(X[15], make_float2(-C1, -S1));
    r4p(X[0],  X[1],  X[2],  X[3]);
    r4p(X[4],  X[5],  X[6],  X[7]);
    r4p(X[8],  X[9],  X[10], X[11]);
    r4p(X[12], X[13], X[14], X[15]);
}

// e^{+2pi i s/32}
__device__ __constant__ float2 CW32P[16] = {
    { 1.0000000000f, 0.0000000000f}, { 0.9807852804f, 0.1950903220f},
    { 0.9238795325f, 0.3826834324f}, { 0.8314696123f, 0.5555702330f},
    { 0.7071067812f, 0.7071067812f}, { 0.5555702330f, 0.8314696123f},
    { 0.3826834324f, 0.9238795325f}, { 0.1950903220f, 0.9807852804f},
    { 0.0000000000f, 1.0000000000f}, {-0.1950903220f, 0.9807852804f},
    {-0.3826834324f, 0.9238795325f}, {-0.5555702330f, 0.8314696123f},
    {-0.7071067812f, 0.7071067812f}, {-0.8314696123f, 0.5555702330f},
    {-0.9238795325f, 0.3826834324f}, {-0.9807852804f, 0.1950903220f}};

// ---------------------------------------------------------------------------
__global__ void prep_kernel(const float* __restrict__ dlnf, unsigned int dlnf_n) {
    const int k = threadIdx.x;
    const int bid = blockIdx.x;
    if (bid < NDL) {
        __shared__ float sidx[KSZ];
        __shared__ float sh_em1, sh_beta;
        if (k == 0) {
            const float beta = (bid < (int)dlnf_n) ? 2.0f * dlnf[bid] : 0.0f;
            sh_beta = beta;
            sh_em1 = (float)exp((double)beta) - 1.0f;   // fast-math-proof
        }
        __syncthreads();
        const float beta = sh_beta, em1 = sh_em1;
        float tsrc;
        if (fabsf(beta) < 1e-8f) {
            tsrc = -1.0f + (float)k * (2.0f / 1023.0f);
        } else {
            const float tau = (float)k * (1.0f / 1023.0f);
            tsrc = (2.0f / beta) * log1pf(tau * em1) - 1.0f;
        }
        sidx[k] = (tsrc + 1.0f) * 0.5f * 1023.0f;
        __syncthreads();
        if (k <= 512)
            g_idx2[bid * IDX2_STRIDE + k] = make_float2(sidx[k], sidx[(1024 - k) & 1023]);
    } else {
        __shared__ float2 schp[KSZ];
        const float kf = (float)k;
        float s, c;
        __sincosf(-6.283185307179586f * kf * (1.0f / 1024.0f), &s, &c);
        g_tw[k] = make_float2(c, s);
        const float t = fmaf(2.0f * (1.0f / 1023.0f), kf, -1.0f);
        __sincosf(-0.5f * t * t, &s, &c);
        schp[k] = make_float2(0.5f * c, 0.5f * s);
        const float h0 = 0.5f * (1.0f - __cosf(6.283185307179586f * kf * (1.0f / 1024.0f)));
        const float h1 = (k < KSZ - 1)
            ? 0.5f * (1.0f - __cosf(6.283185307179586f * (kf + 1.0f) * (1.0f / 1024.0f)))
            : 0.0f;
        g_hpair[k] = make_float2(h0, h1);
        __syncthreads();
        if (k <= 512) {
            const float2 cj  = schp[k];
            const float2 cjj = schp[(1024 - k) & 1023];
            g_chp4[k] = make_float4(cjj.x, cjj.y, cj.x, cj.y);
        }
    }
}

// hermitian base from two resampled values + paired chirp
__device__ __forceinline__ float2 hbase(float r1, float r2, float4 cp) {
    return make_float2(fmaf(r1, cp.z, r2 * cp.x), fmaf(r2, cp.y, -r1 * cp.w));
}

// ---------------------------------------------------------------------------
// One CTA per TWO (b,w) windows; 8 warps; warp = d in {wid, wid+8} x 2 windows.
// Combined float4 window table; step-2 twiddles from the exact g_tw table
// (no iterated chains -> lower reg pressure, no serial FMA chain).
// ---------------------------------------------------------------------------
#define ROWS  17
#define XROWS 33          // row 32 = shifted lane-0 mirror row (uniform pack2)
#define XCHSZ (XROWS * ROWS)   // 561 float2 per warp
__global__ void __launch_bounds__(TPB, 2) stft_kernel(const float* __restrict__ x,
                                                      float* __restrict__ out,
                                                      unsigned int x_n,
                                                      unsigned int cap) {
    extern __shared__ float sm[];
    float4* wp4 = (float4*)sm;                                // 1024 f4 = 16 KB
    const int tid  = threadIdx.x;
    const int lane = tid & 31;
    const int wid  = tid >> 5;
    float2* xch = (float2*)(sm + 4 * KSZ) + (size_t)wid * XCHSZ;

    const int bw0 = 2 * blockIdx.x;
    const int bw1 = bw0 + 1;
    const int b0 = bw0 / WNUM, w0 = bw0 - b0 * WNUM;
    const int b1 = bw1 / WNUM, w1 = bw1 - b1 * WNUM;
    const unsigned int xbase0 = (unsigned int)b0 * 524288u + (unsigned int)w0 * 512u;
    const unsigned int xbase1 = (unsigned int)b1 * 524288u + (unsigned int)w1 * 512u;

    // Build combined windowed table: wp4[k] = (w0[k], w0[k+1], w1[k], w1[k+1])
#pragma unroll
    for (int q = 0; q < 4; q++) {
        const int k = tid + TPB * q;
        const float2 hp = g_hpair[k];
        const unsigned int gi0 = xbase0 + (unsigned int)k;
        const float a0 = (gi0 < x_n) ? x[gi0] : 0.0f;
        const float a1 = (gi0 + 1u < x_n) ? x[gi0 + 1u] : 0.0f;
        const unsigned int gi1 = xbase1 + (unsigned int)k;
        const float c0 = (gi1 < x_n) ? x[gi1] : 0.0f;
        const float c1 = (gi1 + 1u < x_n) ? x[gi1 + 1u] : 0.0f;
        wp4[k] = make_float4(a0 * hp.x, a1 * hp.y, c0 * hp.x, c1 * hp.y);
    }
    const int pa2 = 32 - lane;                                 // 0 -> 32 (mirror row)
    const int r   = lane & 15;
    const int h   = lane >> 4;
    const float2 csgn = h ? C_M1M1 : make_float2(1.f, 1.f);
    __syncthreads();

#pragma unroll 1
    for (int it = 0; it < 2; it++) {
        const int d = wid + 8 * it;
        const float2* id2 = g_idx2 + d * IDX2_STRIDE;

        // ---- pack stage 1 (both windows; tables + lo/frac computed once) ----
        __syncwarp();
        float2 wb0[16], wb1[16];
        float2 h512_0, h512_1;
#pragma unroll
        for (int bq = 0; bq < 16; bq++) {
            const int j = lane + 32 * bq;
            const float2 ix = id2[j];
            const float4 cp = g_chp4[j];
            const int lo1 = clampi((int)ix.x, 0, 1022);
            const float f1 = ix.x - (float)lo1;
            const float4 qa = wp4[lo1];
            const float va0 = fmaf(f1, qa.y - qa.x, qa.x);
            const float va1 = fmaf(f1, qa.w - qa.z, qa.z);
            const int lo2 = clampi((int)ix.y, 0, 1022);
            const float f2 = ix.y - (float)lo2;
            const float4 qb = wp4[lo2];
            const float vb0 = fmaf(f2, qb.y - qb.x, qb.x);
            const float vb1 = fmaf(f2, qb.w - qb.z, qb.z);
            wb0[bq] = hbase(va0, vb0, cp);
            wb1[bq] = hbase(va1, vb1, cp);
            xch[lane * ROWS + bq] = wb0[bq];
            if (lane == 0 && bq >= 1) xch[32 * ROWS + bq - 1] = wb0[bq];
        }
        {
            const float2 ix = id2[512];
            const int lo = clampi((int)ix.x, 0, 1022);
            const float f = ix.x - (float)lo;
            const float4 qa = wp4[lo];
            const float cz2 = 2.0f * g_chp4[512].z;
            h512_0 = make_float2(fmaf(f, qa.y - qa.x, qa.x) * cz2, 0.0f);
            h512_1 = make_float2(fmaf(f, qa.w - qa.z, qa.z) * cz2, 0.0f);
            if (lane == 0) xch[32 * ROWS + 15] = h512_0;
        }
        __syncwarp();

        // ---- pack stage 2, window 0 (cwq from g_tw table, conj folded) ----
#pragma unroll
        for (int bq = 0; bq < 16; bq++) {
            const float2 pm = xch[pa2 * ROWS + 15 - bq];       // h[512-q]
            const float2 wq = wb0[bq];
            const float2 A = f2fma(pm, C_P1M1, wq);
            const float2 D = f2fma(pm, C_M1P1, wq);
            const float2 t = __ldg(&g_tw[lane + 32 * bq]);     // e^{-2pi i q/1024}
            const float2 B = c_mulcj(t, D);                    // e^{+2pi i q/1024} * D
            wb0[bq] = f2fma(make_float2(B.y, B.x), C_M1P1, A);
        }
        __syncwarp();

        // ---- swap in window 1 bases, pack stage 2 window 1 ----
#pragma unroll
        for (int bq = 0; bq < 16; bq++) {
            xch[lane * ROWS + bq] = wb1[bq];
            if (lane == 0 && bq >= 1) xch[32 * ROWS + bq - 1] = wb1[bq];
        }
        if (lane == 0) xch[32 * ROWS + 15] = h512_1;
        __syncwarp();
#pragma unroll
        for (int bq = 0; bq < 16; bq++) {
            const float2 pm = xch[pa2 * ROWS + 15 - bq];
            const float2 wq = wb1[bq];
            const float2 A = f2fma(pm, C_P1M1, wq);
            const float2 D = f2fma(pm, C_M1P1, wq);
            const float2 t = __ldg(&g_tw[lane + 32 * bq]);
            const float2 B = c_mulcj(t, D);
            wb1[bq] = f2fma(make_float2(B.y, B.x), C_M1P1, A);
        }

        // ---- FFT + store, window 0 then window 1 ----
#pragma unroll
        for (int win = 0; win < 2; win++) {
            float2* wb = win ? wb1 : wb0;
            const int bwc = win ? bw1 : bw0;

            dft16p(wb);
            __syncwarp();
            {   // step 2: twiddle e^{+2pi i lane*rr/512} = conj(g_tw[(2*lane*rr)&1023])
                xch[lane * ROWS + 0] = wb[0];
#pragma unroll
                for (int rr = 1; rr < 16; rr++) {
                    const float2 t = __ldg(&g_tw[(2 * lane * rr) & 1023]);
                    xch[lane * ROWS + rr] = c_mulcj(t, wb[F16(rr)]);
                }
            }
            __syncwarp();

            float2 G[16];
#pragma unroll
            for (int j = 0; j < 16; j++)
                G[j] = xch[(2 * j + h) * ROWS + r];
            dft16p(G);
            __syncwarp();   // xch reads done before next win/it overwrites

            const unsigned int obase =
                ((unsigned int)d * (BNUM * WNUM) + (unsigned int)bwc) * KSZ;
            if (cap >= TOTAL_FLOATS) {
#pragma unroll
                for (int s = 0; s < 16; s++) {
                    const int sp = F16(s);
                    const float2 own = G[s];
                    float2 oth;
                    oth.x = __shfl_xor_sync(0xffffffffu, own.x, 16);
                    oth.y = __shfl_xor_sync(0xffffffffu, own.y, 16);
                    const float2 E = h ? oth : own;
                    const float2 O = h ? own : oth;
                    const float2 WO = c_mul(O, CW32P[sp]);
                    const float2 res = f2fma(WO, csgn, E);
                    const unsigned int fo = obase + 2u * (unsigned int)(r + 16 * sp + 256 * h);
                    *(float2*)(out + fo) = res;
                }
            } else {
#pragma unroll
                for (int s = 0; s < 16; s++) {
                    const int sp = F16(s);
                    const float2 own = G[s];
                    float2 oth;
                    oth.x = __shfl_xor_sync(0xffffffffu, own.x, 16);
                    oth.y = __shfl_xor_sync(0xffffffffu, own.y, 16);
                    const float2 E = h ? oth : own;
                    const float2 O = h ? own : oth;
                    const float2 WO = c_mul(O, CW32P[sp]);
                    const float2 res = f2fma(WO, csgn, E);
                    const unsigned int fo = obase + 2u * (unsigned int)(r + 16 * sp + 256 * h);
                    if (fo + 1u < cap) {
                        *(float2*)(out + fo) = res;
                    } else if (fo < cap) {
                        out[fo] = res.x;
                    }
                }
            }
        }
    }
}

#define SMEM_BYTES (KSZ * 16 + 8 * XCHSZ * 8)   // 16384 + 35904 = 52288

// ---------------------------------------------------------------------------
extern "C" void kernel_launch(void* const* d_in, const int* in_sizes, int n_in,
                              void* d_out, int out_size) {
    if (!d_in || !in_sizes || !d_out || n_in < 1) return;

    const float* x = nullptr;   long long xn = -1;
    const float* dl = nullptr;  long long dn = 0;
    for (int i = 0; i < n_in; i++) {
        if (!d_in[i]) continue;
        if ((long long)in_sizes[i] > xn) { xn = in_sizes[i]; x = (const float*)d_in[i]; }
    }
    for (int i = 0; i < n_in; i++) {
        if (!d_in[i] || (const float*)d_in[i] == x) continue;
        dl = (const float*)d_in[i]; dn = in_sizes[i];
    }
    if (!x || xn <= 0) return;
    if (!dl) { dl = x; dn = 0; }

    long long cap = (long long)out_size;
    if (cap > (long long)TOTAL_FLOATS) cap = TOTAL_FLOATS;
    if (cap < 0) cap = 0;

    cudaFuncSetAttribute(stft_kernel, cudaFuncAttributeMaxDynamicSharedMemorySize, SMEM_BYTES);

    prep_kernel<<<NDL + 1, KSZ>>>(dl, (unsigned int)dn);
    stft_kernel<<<(BNUM * WNUM) / 2, TPB, SMEM_BYTES>>>(x, (float*)d_out,
                                                        (unsigned int)xn, (unsigned int)cap);
}

// round 16
// speedup vs baseline: 1.6431x; 1.0996x over previous
#include <cuda_runtime.h>
#include <math.h>

#define KSZ   1024
#define WNUM  1023
#define BNUM  2
#define NDL   16
#define TPB   256
#define TOTAL_FLOATS 33521664u   // 16 * 2 * 1023 * 1024 real-part floats
#define IDX2_STRIDE 520

__device__ float2 g_idx2[NDL * IDX2_STRIDE];  // (idx[j], idx[(1024-j)&1023]), j<=512
__device__ float4 g_chp4[IDX2_STRIDE];        // (chp[jj].x, chp[jj].y, chp[j].x, chp[j].y)
__device__ float2 g_tw[KSZ];                  // e^{-2pi i r/1024}
__device__ float2 g_hpair[KSZ];               // (hann[k], hann[k+1])

__device__ __forceinline__ float2 c_mul(float2 a, float2 b) {
    return make_float2(fmaf(a.x, b.x, -a.y * b.y), fmaf(a.x, b.y, a.y * b.x));
}
// conj(t) * d  (4 FMA, conj folded)
__device__ __forceinline__ float2 c_mulcj(float2 t, float2 d) {
    return make_float2(fmaf(t.x, d.x, t.y * d.y), fmaf(t.x, d.y, -t.y * d.x));
}
__device__ __forceinline__ int clampi(int v, int lo, int hi) {
    return v < lo ? lo : (v > hi ? hi : v);
}

// ---- packed f32x2 primitives (emit Blackwell FFMA2 / FADD2) ----
__device__ __forceinline__ float2 f2add(float2 a, float2 b) {
    float2 d;
    asm("{\n\t.reg .b64 ra, rb, rd;\n\t"
        "mov.b64 ra, {%2, %3};\n\tmov.b64 rb, {%4, %5};\n\t"
        "add.rn.f32x2 rd, ra, rb;\n\t"
        "mov.b64 {%0, %1}, rd;\n\t}"
        : "=f"(d.x), "=f"(d.y)
        : "f"(a.x), "f"(a.y), "f"(b.x), "f"(b.y));
    return d;
}
__device__ __forceinline__ float2 f2fma(float2 a, float2 b, float2 c) {  // a*b + c
    float2 d;
    asm("{\n\t.reg .b64 ra, rb, rc, rd;\n\t"
        "mov.b64 ra, {%2, %3};\n\tmov.b64 rb, {%4, %5};\n\tmov.b64 rc, {%6, %7};\n\t"
        "fma.rn.f32x2 rd, ra, rb, rc;\n\t"
        "mov.b64 {%0, %1}, rd;\n\t}"
        : "=f"(d.x), "=f"(d.y)
        : "f"(a.x), "f"(a.y), "f"(b.x), "f"(b.y), "f"(c.x), "f"(c.y));
    return d;
}
#define C_M1M1 make_float2(-1.f, -1.f)
#define C_M1P1 make_float2(-1.f,  1.f)
#define C_P1M1 make_float2( 1.f, -1.f)
__device__ __forceinline__ float2 f2sub(float2 a, float2 b) { return f2fma(b, C_M1M1, a); }

// dft16 slot<->frequency involution
__device__ __forceinline__ constexpr int F16(int s) { return (s >> 2) + 4 * (s & 3); }

// positive-sign radix-4 butterfly (w4 = +i), packed
__device__ __forceinline__ void r4p(float2& x0, float2& x1, float2& x2, float2& x3) {
    const float2 t0 = f2add(x0, x2), t1 = f2sub(x0, x2);
    const float2 t2 = f2add(x1, x3), bd = f2sub(x1, x3);
    const float2 bds = make_float2(bd.y, bd.x);
    x0 = f2add(t0, t2);
    x2 = f2sub(t0, t2);
    x1 = f2fma(bds, C_M1P1, t1);
    x3 = f2fma(bds, C_P1M1, t1);
}

// 16-point POSITIVE DFT in registers; Y[F16(s)] lands in slot s.
__device__ __forceinline__ void dft16p(float2 X[16]) {
    r4p(X[0], X[4], X[8],  X[12]);
    r4p(X[1], X[5], X[9],  X[13]);
    r4p(X[2], X[6], X[10], X[14]);
    r4p(X[3], X[7], X[11], X[15]);
    const float C1 = 0.9238795325112867f, S1 = 0.3826834323650898f, R2 = 0.7071067811865476f;
    X[5]  = c_mul(X[5],  make_float2( C1,  S1));
    X[9]  = c_mul(X[9],  make_float2( R2,  R2));
    X[13] = c_mul(X[13], make_float2( S1,  C1));
    X[6]  = c_mul(X[6],  make_float2( R2,  R2));
    X[10] = make_float2(-X[10].y, X[10].x);
    X[14] = c_mul(X[14], make_float2(-R2,  R2));
    X[7]  = c_mul(X[7],  make_float2( S1,  C1));
    X[11] = c_mul(X[11], make_float2(-R2,  R2));
    X[15] = c_mul(X[15], make_float2(-C1, -S1));
    r4p(X[0],  X[1],  X[2],  X[3]);
    r4p(X[4],  X[5],  X[6],  X[7]);
    r4p(X[8],  X[9],  X[10], X[11]);
    r4p(X[12], X[13], X[14], X[15]);
}

// e^{+2pi i s/32}
__device__ __constant__ float2 CW32P[16] = {
    { 1.0000000000f, 0.0000000000f}, { 0.9807852804f, 0.1950903220f},
    { 0.9238795325f, 0.3826834324f}, { 0.8314696123f, 0.5555702330f},
    { 0.7071067812f, 0.7071067812f}, { 0.5555702330f, 0.8314696123f},
    { 0.3826834324f, 0.9238795325f}, { 0.1950903220f, 0.9807852804f},
    { 0.0000000000f, 1.0000000000f}, {-0.1950903220f, 0.9807852804f},
    {-0.3826834324f, 0.9238795325f}, {-0.5555702330f, 0.8314696123f},
    {-0.7071067812f, 0.7071067812f}, {-0.8314696123f, 0.5555702330f},
    {-0.9238795325f, 0.3826834324f}, {-0.9807852804f, 0.1950903220f}};

// ---------------------------------------------------------------------------
__global__ void prep_kernel(const float* __restrict__ dlnf, unsigned int dlnf_n) {
    const int k = threadIdx.x;
    const int bid = blockIdx.x;
    if (bid < NDL) {
        __shared__ float sidx[KSZ];
        __shared__ float sh_em1, sh_beta;
        if (k == 0) {
            const float beta = (bid < (int)dlnf_n) ? 2.0f * dlnf[bid] : 0.0f;
            sh_beta = beta;
            sh_em1 = (float)exp((double)beta) - 1.0f;   // fast-math-proof
        }
        __syncthreads();
        const float beta = sh_beta, em1 = sh_em1;
        float tsrc;
        if (fabsf(beta) < 1e-8f) {
            tsrc = -1.0f + (float)k * (2.0f / 1023.0f);
        } else {
            const float tau = (float)k * (1.0f / 1023.0f);
            tsrc = (2.0f / beta) * log1pf(tau * em1) - 1.0f;
        }
        sidx[k] = (tsrc + 1.0f) * 0.5f * 1023.0f;
        __syncthreads();
        if (k <= 512)
            g_idx2[bid * IDX2_STRIDE + k] = make_float2(sidx[k], sidx[(1024 - k) & 1023]);
    } else {
        __shared__ float2 schp[KSZ];
        const float kf = (float)k;
        float s, c;
        __sincosf(-6.283185307179586f * kf * (1.0f / 1024.0f), &s, &c);
        g_tw[k] = make_float2(c, s);
        const float t = fmaf(2.0f * (1.0f / 1023.0f), kf, -1.0f);
        __sincosf(-0.5f * t * t, &s, &c);
        schp[k] = make_float2(0.5f * c, 0.5f * s);
        const float h0 = 0.5f * (1.0f - __cosf(6.283185307179586f * kf * (1.0f / 1024.0f)));
        const float h1 = (k < KSZ - 1)
            ? 0.5f * (1.0f - __cosf(6.283185307179586f * (kf + 1.0f) * (1.0f / 1024.0f)))
            : 0.0f;
        g_hpair[k] = make_float2(h0, h1);
        __syncthreads();
        if (k <= 512) {
            const float2 cj  = schp[k];
            const float2 cjj = schp[(1024 - k) & 1023];
            g_chp4[k] = make_float4(cjj.x, cjj.y, cj.x, cj.y);
        }
    }
}

// hermitian base from two resampled values + paired chirp
__device__ __forceinline__ float2 hbase(float r1, float r2, float4 cp) {
    return make_float2(fmaf(r1, cp.z, r2 * cp.x), fmaf(r2, cp.y, -r1 * cp.w));
}
// pack2 combine: U = A + i*conj(t)*D with A = wq + conj(pm), D = wq - conj(pm)
__device__ __forceinline__ float2 packU(float2 wq, float2 pm, float2 t) {
    const float2 A = f2fma(pm, C_P1M1, wq);
    const float2 D = f2fma(pm, C_M1P1, wq);
    const float2 B = c_mulcj(t, D);
    return f2fma(make_float2(B.y, B.x), C_M1P1, A);
}

// ---------------------------------------------------------------------------
// One CTA per TWO (b,w) windows; 8 warps; warp = d in {wid, wid+8} x 2 windows.
// Pack exchange fused: float4 xch stores (wb0, wb1) interleaved -> one smem
// round + one g_tw load serve both windows. FFT phases identical to R13.
// ---------------------------------------------------------------------------
#define ROWS  17
#define XROWS 33          // row 32 = shifted lane-0 mirror row (uniform pack2)
#define XCH4SZ (XROWS * ROWS)     // 561 float4 per warp = 8976 B
__global__ void __launch_bounds__(TPB, 2) stft_kernel(const float* __restrict__ x,
                                                      float* __restrict__ out,
                                                      unsigned int x_n,
                                                      unsigned int cap) {
    extern __shared__ float sm[];
    float4* wp4 = (float4*)sm;                                // 1024 f4 = 16 KB
    const int tid  = threadIdx.x;
    const int lane = tid & 31;
    const int wid  = tid >> 5;
    float4* xch4 = (float4*)(sm + 4 * KSZ) + (size_t)wid * XCH4SZ;
    float2* xch  = (float2*)xch4;            // aliased for FFT exchange (ROWS=17)

    const int bw0 = 2 * blockIdx.x;
    const int bw1 = bw0 + 1;
    const int b0 = bw0 / WNUM, w0 = bw0 - b0 * WNUM;
    const int b1 = bw1 / WNUM, w1 = bw1 - b1 * WNUM;
    const unsigned int xbase0 = (unsigned int)b0 * 524288u + (unsigned int)w0 * 512u;
    const unsigned int xbase1 = (unsigned int)b1 * 524288u + (unsigned int)w1 * 512u;

    // Build combined windowed table: wp4[k] = (w0[k], w0[k+1], w1[k], w1[k+1])
#pragma unroll
    for (int q = 0; q < 4; q++) {
        const int k = tid + TPB * q;
        const float2 hp = g_hpair[k];
        const unsigned int gi0 = xbase0 + (unsigned int)k;
        const float a0 = (gi0 < x_n) ? x[gi0] : 0.0f;
        const float a1 = (gi0 + 1u < x_n) ? x[gi0 + 1u] : 0.0f;
        const unsigned int gi1 = xbase1 + (unsigned int)k;
        const float c0 = (gi1 < x_n) ? x[gi1] : 0.0f;
        const float c1 = (gi1 + 1u < x_n) ? x[gi1 + 1u] : 0.0f;
        wp4[k] = make_float4(a0 * hp.x, a1 * hp.y, c0 * hp.x, c1 * hp.y);
    }
    const float2 g2 = g_tw[2 * lane];
    const float2 base = make_float2(g2.x, -g2.y);              // e^{+2pi i lane/512}
    const float2 b2 = c_mul(base, base);
    const float2 b3 = c_mul(b2, base);
    const float2 b4 = c_mul(b2, b2);
    const int pa2 = 32 - lane;                                 // 0 -> 32 (mirror row)
    const int r   = lane & 15;
    const int h   = lane >> 4;
    const float2 csgn = h ? C_M1M1 : make_float2(1.f, 1.f);
    __syncthreads();

#pragma unroll 1
    for (int it = 0; it < 2; it++) {
        const int d = wid + 8 * it;
        const float2* id2 = g_idx2 + d * IDX2_STRIDE;

        // ---- pack stage 1: both windows into float4 xch (one STS.128/bq) ----
        __syncwarp();    // previous iteration's xch reads complete
        float2 wb0[16], wb1[16];
#pragma unroll
        for (int bq = 0; bq < 16; bq++) {
            const int j = lane + 32 * bq;
            const float2 ix = id2[j];
            const float4 cp = g_chp4[j];
            const int lo1 = clampi((int)ix.x, 0, 1022);
            const float f1 = ix.x - (float)lo1;
            const float4 qa = wp4[lo1];
            const float va0 = fmaf(f1, qa.y - qa.x, qa.x);
            const float va1 = fmaf(f1, qa.w - qa.z, qa.z);
            const int lo2 = clampi((int)ix.y, 0, 1022);
            const float f2 = ix.y - (float)lo2;
            const float4 qb = wp4[lo2];
            const float vb0 = fmaf(f2, qb.y - qb.x, qb.x);
            const float vb1 = fmaf(f2, qb.w - qb.z, qb.z);
            wb0[bq] = hbase(va0, vb0, cp);
            wb1[bq] = hbase(va1, vb1, cp);
            xch4[lane * ROWS + bq] = make_float4(wb0[bq].x, wb0[bq].y, wb1[bq].x, wb1[bq].y);
            if (lane == 0 && bq >= 1)
                xch4[32 * ROWS + bq - 1] = make_float4(wb0[bq].x, wb0[bq].y, wb1[bq].x, wb1[bq].y);
        }
        {
            const float2 ix = id2[512];
            const int lo = clampi((int)ix.x, 0, 1022);
            const float f = ix.x - (float)lo;
            const float4 qa = wp4[lo];
            const float cz2 = 2.0f * g_chp4[512].z;
            if (lane == 0)
                xch4[32 * ROWS + 15] = make_float4(fmaf(f, qa.y - qa.x, qa.x) * cz2, 0.0f,
                                                   fmaf(f, qa.w - qa.z, qa.z) * cz2, 0.0f);
        }
        __syncwarp();

        // ---- pack stage 2: both windows (one LDS.128 mirror + one g_tw load) ----
#pragma unroll
        for (int bq = 0; bq < 16; bq++) {
            const float4 pm4 = xch4[pa2 * ROWS + 15 - bq];     // h[512-q] (win0, win1)
            const float2 t = __ldg(&g_tw[lane + 32 * bq]);     // e^{-2pi i q/1024}
            wb0[bq] = packU(wb0[bq], make_float2(pm4.x, pm4.y), t);
            wb1[bq] = packU(wb1[bq], make_float2(pm4.z, pm4.w), t);
        }

        // ---- FFT + store, window 0 then window 1 (R13 structure) ----
#pragma unroll
        for (int win = 0; win < 2; win++) {
            float2* wb = win ? wb1 : wb0;
            const int bwc = win ? bw1 : bw0;

            dft16p(wb);
            __syncwarp();    // pack2 / previous win's gather reads complete
            {   // step 2: twiddle base^rr via 4 iterated chains (R13-proven)
                float2 t1 = base, t2 = b2, t3 = b3, t4 = b4;
                xch[lane * ROWS + 0] = wb[0];
#pragma unroll
                for (int rr = 1; rr < 16; rr++) {
                    float2 wc;
                    switch (rr & 3) {
                        case 1: wc = t1; if (rr < 12) t1 = c_mul(t1, b4); break;
                        case 2: wc = t2; if (rr < 12) t2 = c_mul(t2, b4); break;
                        case 3: wc = t3; if (rr < 12) t3 = c_mul(t3, b4); break;
                        default: wc = t4; if (rr < 12) t4 = c_mul(t4, b4); break;
                    }
                    xch[lane * ROWS + rr] = c_mul(wb[F16(rr)], wc);
                }
            }
            __syncwarp();

            float2 G[16];
#pragma unroll
            for (int j = 0; j < 16; j++)
                G[j] = xch[(2 * j + h) * ROWS + r];
            dft16p(G);
            __syncwarp();   // xch reads done before next win/it overwrites

            const unsigned int obase =
                ((unsigned int)d * (BNUM * WNUM) + (unsigned int)bwc) * KSZ;
            if (cap >= TOTAL_FLOATS) {
#pragma unroll
                for (int s = 0; s < 16; s++) {
                    const int sp = F16(s);
                    const float2 own = G[s];
                    float2 oth;
                    oth.x = __shfl_xor_sync(0xffffffffu, own.x, 16);
                    oth.y = __shfl_xor_sync(0xffffffffu, own.y, 16);
                    const float2 E = h ? oth : own;
                    const float2 O = h ? own : oth;
                    const float2 WO = c_mul(O, CW32P[sp]);
                    const float2 res = f2fma(WO, csgn, E);
                    const unsigned int fo = obase + 2u * (unsigned int)(r + 16 * sp + 256 * h);
                    *(float2*)(out + fo) = res;
                }
            } else {
#pragma unroll
                for (int s = 0; s < 16; s++) {
                    const int sp = F16(s);
                    const float2 own = G[s];
                    float2 oth;
                    oth.x = __shfl_xor_sync(0xffffffffu, own.x, 16);
                    oth.y = __shfl_xor_sync(0xffffffffu, own.y, 16);
                    const float2 E = h ? oth : own;
                    const float2 O = h ? own : oth;
                    const float2 WO = c_mul(O, CW32P[sp]);
                    const float2 res = f2fma(WO, csgn, E);
                    const unsigned int fo = obase + 2u * (unsigned int)(r + 16 * sp + 256 * h);
                    if (fo + 1u < cap) {
                        *(float2*)(out + fo) = res;
                    } else if (fo < cap) {
                        out[fo] = res.x;
                    }
                }
            }
        }
    }
}

#define SMEM_BYTES (KSZ * 16 + 8 * XCH4SZ * 16)   // 16384 + 71808 = 88192

// ---------------------------------------------------------------------------
extern "C" void kernel_launch(void* const* d_in, const int* in_sizes, int n_in,
                              void* d_out, int out_size) {
    if (!d_in || !in_sizes || !d_out || n_in < 1) return;

    const float* x = nullptr;   long long xn = -1;
    const float* dl = nullptr;  long long dn = 0;
    for (int i = 0; i < n_in; i++) {
        if (!d_in[i]) continue;
        if ((long long)in_sizes[i] > xn) { xn = in_sizes[i]; x = (const float*)d_in[i]; }
    }
    for (int i = 0; i < n_in; i++) {
        if (!d_in[i] || (const float*)d_in[i] == x) continue;
        dl = (const float*)d_in[i]; dn = in_sizes[i];
    }
    if (!x || xn <= 0) return;
    if (!dl) { dl = x; dn = 0; }

    long long cap = (long long)out_size;
    if (cap > (long long)TOTAL_FLOATS) cap = TOTAL_FLOATS;
    if (cap < 0) cap = 0;

    cudaFuncSetAttribute(stft_kernel, cudaFuncAttributeMaxDynamicSharedMemorySize, SMEM_BYTES);

    prep_kernel<<<NDL + 1, KSZ>>>(dl, (unsigned int)dn);
    stft_kernel<<<(BNUM * WNUM) / 2, TPB, SMEM_BYTES>>>(x, (float*)d_out,
                                                        (unsigned int)xn, (unsigned int)cap);
}